// round 11
// baseline (speedup 1.0000x reference)
#include <cuda_runtime.h>
#include <cuda_fp16.h>
#include <cstdint>

#define NN 16384
#define DD 64
#define KK 64            // plain fp16 GEMM: a . w (residual dropped; well under tolerance)
#define SROW 128         // smem row stride bytes (8 x 16B chunks) for both operands

constexpr float TAU_F   = 0.28f;
constexpr float EPS_F   = 1e-8f;
constexpr float LOG2E_F = 1.4426950408889634f;

// Scratch (allocation-free: __device__ globals)
__device__ __half g_a[NN * KK];               // A rows: fp16(u_n * log2e/TAU)
__device__ __half g_b[NN * KK];               // B rows: fp16(u_n + i_n)
__device__ float g_pos[NN];
__device__ float g_partial[(NN / 128) * NN];  // per-column-block partial row sums
__device__ float g_blocksum[64];

__device__ __forceinline__ uint32_t smem_u32(const void* p) {
    uint32_t a;
    asm("{ .reg .u64 t; cvta.to.shared.u64 t, %1; cvt.u32.u64 %0, t; }" : "=r"(a) : "l"(p));
    return a;
}
__device__ __forceinline__ void cp16(uint32_t saddr, const void* g) {
    asm volatile("cp.async.cg.shared.global [%0], [%1], 16;" :: "r"(saddr), "l"(g));
}
__device__ __forceinline__ void ldsm_x4(uint32_t* r, uint32_t addr) {
    asm volatile("ldmatrix.sync.aligned.m8n8.x4.shared.b16 {%0,%1,%2,%3}, [%4];"
                 : "=r"(r[0]), "=r"(r[1]), "=r"(r[2]), "=r"(r[3]) : "r"(addr));
}
__device__ __forceinline__ void mma16816(float* c, const uint32_t* a,
                                         uint32_t b0, uint32_t b1) {
    asm volatile(
        "mma.sync.aligned.m16n8k16.row.col.f32.f16.f16.f32 "
        "{%0,%1,%2,%3}, {%4,%5,%6,%7}, {%8,%9}, {%0,%1,%2,%3};"
        : "+f"(c[0]), "+f"(c[1]), "+f"(c[2]), "+f"(c[3])
        : "r"(a[0]), "r"(a[1]), "r"(a[2]), "r"(a[3]), "r"(b0), "r"(b1));
}
// Pack two fp32 into f16x2 (both halves end up summed into the same row sum,
// so half ordering is irrelevant).
__device__ __forceinline__ uint32_t packh2(float x, float y) {
    uint32_t h;
    asm("cvt.rn.f16x2.f32 %0, %1, %2;" : "=r"(h) : "f"(y), "f"(x));
    return h;
}
__device__ __forceinline__ uint32_t ex2h2(uint32_t v) {
    uint32_t r;
    asm volatile("ex2.approx.f16x2 %0, %1;" : "=r"(r) : "r"(v));
    return r;
}
__device__ __forceinline__ uint32_t hadd2(uint32_t a, uint32_t b) {
    uint32_t r;
    asm("add.rn.f16x2 %0, %1, %2;" : "=r"(r) : "r"(a), "r"(b));
    return r;
}
__device__ __forceinline__ float unpack_sum(uint32_t v) {
    float lo, hi;
    asm("{ .reg .b16 l, h; mov.b32 {l, h}, %2;\n\t"
        "  cvt.f32.f16 %0, l; cvt.f32.f16 %1, h; }"
        : "=f"(lo), "=f"(hi) : "r"(v));
    return lo + hi;
}

// ---------------------------------------------------------------------------
// Kernel 1: normalize, build fp16 A (scaled) and B (w = u_n + i_n).
// ---------------------------------------------------------------------------
__global__ void prep_kernel(const float* __restrict__ U, const float* __restrict__ I) {
    int row  = blockIdx.x * 8 + (threadIdx.x >> 5);
    int lane = threadIdx.x & 31;

    const float* up = U + (size_t)row * DD;
    const float* ip = I + (size_t)row * DD;
    float u0 = up[lane], u1 = up[lane + 32];
    float i0 = ip[lane], i1 = ip[lane + 32];

    float su = u0 * u0 + u1 * u1;
    float si = i0 * i0 + i1 * i1;
#pragma unroll
    for (int o = 16; o; o >>= 1) {
        su += __shfl_xor_sync(0xffffffffu, su, o);
        si += __shfl_xor_sync(0xffffffffu, si, o);
    }
    float inu = rsqrtf(fmaxf(su, 1e-24f));
    float ini = rsqrtf(fmaxf(si, 1e-24f));

    float un0 = u0 * inu, un1 = u1 * inu;
    float vn0 = i0 * ini, vn1 = i1 * ini;

    float d = un0 * vn0 + un1 * vn1;
#pragma unroll
    for (int o = 16; o; o >>= 1) d += __shfl_xor_sync(0xffffffffu, d, o);

    const float SC = LOG2E_F / TAU_F;   // GEMM output directly = log2 of each exp term
    size_t base = (size_t)row * KK;
    g_a[base + lane]      = __float2half_rn(un0 * SC);
    g_a[base + 32 + lane] = __float2half_rn(un1 * SC);
    g_b[base + lane]      = __float2half_rn(un0 + vn0);
    g_b[base + 32 + lane] = __float2half_rn(un1 + vn1);

    if (lane == 0) g_pos[row] = d * (1.0f / TAU_F);
}

// ---------------------------------------------------------------------------
// Kernel 2: fp16 mma.sync GEMM, 128x128 tile, K=64 resident in smem,
// ldmatrix fragment loads. Epilogue uses ex2.approx.f16x2 (2 exps/MUFU op)
// with 4-term f16x2 partial sums folded into fp32 row sums.
// 8 warps 2(M) x 4(N); warp tile 64x32.
// ---------------------------------------------------------------------------
__global__ void __launch_bounds__(256, 2) gemm_exp_kernel() {
    extern __shared__ __align__(16) char smem[];
    const uint32_t sb = smem_u32(smem);
    const uint32_t sA = sb;                    // 16 KB
    const uint32_t sB = sb + 128 * SROW;       // 16 KB

    const int tid  = threadIdx.x;
    const int wid  = tid >> 5;
    const int lane = tid & 31;
    const int wm   = wid >> 2;                 // 0..1
    const int wn   = wid & 3;                  // 0..3
    const int bm = blockIdx.y, bn = blockIdx.x;

    const char* Ag = (const char*)g_a + (size_t)bm * 128 * (KK * 2);
    const char* Bg = (const char*)g_b + (size_t)bn * 128 * (KK * 2);

    // Load both tiles: 128 rows x 8 chunks(16B) each operand.
#pragma unroll
    for (int it = 0; it < 4; it++) {
        int idx = it * 256 + tid;              // 0..1023
        int row = idx >> 3;
        int c   = idx & 7;
        uint32_t sw = (uint32_t)(row * SROW + ((c ^ (row & 7)) << 4));
        size_t   go = (size_t)row * (KK * 2) + c * 16;
        cp16(sA + sw, Ag + go);
        cp16(sB + sw, Bg + go);
    }
    asm volatile("cp.async.commit_group;" ::: "memory");

    float acc[4][4][4];
#pragma unroll
    for (int i = 0; i < 4; i++)
#pragma unroll
        for (int j = 0; j < 4; j++)
#pragma unroll
            for (int r = 0; r < 4; r++) acc[i][j][r] = 0.f;

    asm volatile("cp.async.wait_group 0;" ::: "memory");
    __syncthreads();

    const int lr16 = lane & 15;                // ldmatrix row within 16
    const int lhi  = lane >> 4;                // k-chunk half select

#pragma unroll
    for (int ks = 0; ks < KK / 16; ks++) {     // 4 k-steps
        const int ch = 2 * ks + lhi;           // 16B chunk index (0..7)
        uint32_t a[4][4];
#pragma unroll
        for (int mf = 0; mf < 4; mf++) {
            int row = wm * 64 + mf * 16 + lr16;
            ldsm_x4(a[mf], sA + row * SROW + ((ch ^ (row & 7)) << 4));
        }
        uint32_t bfr[2][4];
#pragma unroll
        for (int p = 0; p < 2; p++) {
            int row = wn * 32 + p * 16 + lr16;
            ldsm_x4(bfr[p], sB + row * SROW + ((ch ^ (row & 7)) << 4));
        }
        // bfr[p] = {b0(nf=2p), b0(nf=2p+1), b1(nf=2p), b1(nf=2p+1)}
#pragma unroll
        for (int mf = 0; mf < 4; mf++) {
            mma16816(acc[mf][0], a[mf], bfr[0][0], bfr[0][2]);
            mma16816(acc[mf][1], a[mf], bfr[0][1], bfr[0][3]);
            mma16816(acc[mf][2], a[mf], bfr[1][0], bfr[1][2]);
            mma16816(acc[mf][3], a[mf], bfr[1][1], bfr[1][3]);
        }
    }

    // ------- Epilogue: f16x2 exp2 (2 exps per MUFU op) + row sums -------
    // Row g holds acc[..][..][0,1]; row g+8 holds acc[..][..][2,3].
    const int g  = lane >> 2;
    const int t4 = lane & 3;
    float rs0[4], rs1[4];
#pragma unroll
    for (int mf = 0; mf < 4; mf++) {
        uint32_t p0[4], p1[4];
#pragma unroll
        for (int nf = 0; nf < 4; nf++) {
            p0[nf] = ex2h2(packh2(acc[mf][nf][0], acc[mf][nf][1]));
            p1[nf] = ex2h2(packh2(acc[mf][nf][2], acc[mf][nf][3]));
        }
        uint32_t s0 = hadd2(hadd2(p0[0], p0[1]), hadd2(p0[2], p0[3]));
        uint32_t s1 = hadd2(hadd2(p1[0], p1[1]), hadd2(p1[2], p1[3]));
        rs0[mf] = unpack_sum(s0);
        rs1[mf] = unpack_sum(s1);
    }
#pragma unroll
    for (int mf = 0; mf < 4; mf++) {
        rs0[mf] += __shfl_xor_sync(0xffffffffu, rs0[mf], 1);
        rs0[mf] += __shfl_xor_sync(0xffffffffu, rs0[mf], 2);
        rs1[mf] += __shfl_xor_sync(0xffffffffu, rs1[mf], 1);
        rs1[mf] += __shfl_xor_sync(0xffffffffu, rs1[mf], 2);
    }

    __syncthreads();                           // tiles no longer needed; reuse smem
    float* red = (float*)smem;                 // [128 rows][4 wn]
    if (t4 == 0) {
#pragma unroll
        for (int mf = 0; mf < 4; mf++) {
            int r0 = wm * 64 + mf * 16 + g;
            red[r0 * 4 + wn]       = rs0[mf];
            red[(r0 + 8) * 4 + wn] = rs1[mf];
        }
    }
    __syncthreads();
    if (tid < 128) {
        float s = (red[tid * 4 + 0] + red[tid * 4 + 1]) +
                  (red[tid * 4 + 2] + red[tid * 4 + 3]);
        g_partial[(size_t)bn * NN + bm * 128 + tid] = s;   // fixed order, no atomics
    }
}

// ---------------------------------------------------------------------------
// Kernel 3: per-row total over 128 column-block partials, loss, block sums.
// ---------------------------------------------------------------------------
__global__ void reduce_kernel() {
    int r = blockIdx.x * blockDim.x + threadIdx.x;
    float t = 0.f;
#pragma unroll 8
    for (int cb = 0; cb < NN / 128; cb++) t += g_partial[(size_t)cb * NN + r];
    float lr = logf(t + EPS_F) - g_pos[r];

    __shared__ float sm[256];
    sm[threadIdx.x] = lr;
    __syncthreads();
    for (int o = 128; o; o >>= 1) {
        if (threadIdx.x < o) sm[threadIdx.x] += sm[threadIdx.x + o];
        __syncthreads();
    }
    if (threadIdx.x == 0) g_blocksum[blockIdx.x] = sm[0];
}

__global__ void final_kernel(float* __restrict__ out) {
    __shared__ float sm[64];
    int t = threadIdx.x;
    sm[t] = g_blocksum[t];
    __syncthreads();
    for (int o = 32; o; o >>= 1) {
        if (t < o) sm[t] += sm[t + o];
        __syncthreads();
    }
    if (t == 0) out[0] = sm[0] * (1.0f / (float)NN);
}

// ---------------------------------------------------------------------------
extern "C" void kernel_launch(void* const* d_in, const int* in_sizes, int n_in,
                              void* d_out, int out_size) {
    const float* U = (const float*)d_in[0];
    const float* I = (const float*)d_in[1];
    float* out = (float*)d_out;

    const int SMEM_BYTES = 2 * 128 * SROW;     // 32768
    cudaFuncSetAttribute(gemm_exp_kernel,
                         cudaFuncAttributeMaxDynamicSharedMemorySize, SMEM_BYTES);

    prep_kernel<<<NN / 8, 256>>>(U, I);

    dim3 grid(NN / 128, NN / 128);
    gemm_exp_kernel<<<grid, 256, SMEM_BYTES>>>();

    reduce_kernel<<<NN / 256, 256>>>();
    final_kernel<<<1, 64>>>(out);
}

// round 12
// speedup vs baseline: 1.2051x; 1.2051x over previous
#include <cuda_runtime.h>
#include <cuda_fp16.h>
#include <cstdint>

#define NN 16384
#define DD 64
#define KK 64            // plain fp16 GEMM: a . w (residual dropped)
#define SROW 128         // smem row stride bytes (8 x 16B chunks) for both operands

constexpr float TAU_F   = 0.28f;
constexpr float EPS_F   = 1e-8f;
constexpr float LOG2E_F = 1.4426950408889634f;

// Scratch (allocation-free: __device__ globals)
__device__ __half g_a[NN * KK];               // A rows: fp16(u_n * log2e/TAU)
__device__ __half g_b[NN * KK];               // B rows: fp16(u_n + i_n)
__device__ float g_pos[NN];
__device__ float g_partial[(NN / 128) * NN];  // per-column-block partial row sums
__device__ float g_blocksum[64];

__device__ __forceinline__ uint32_t smem_u32(const void* p) {
    uint32_t a;
    asm("{ .reg .u64 t; cvta.to.shared.u64 t, %1; cvt.u32.u64 %0, t; }" : "=r"(a) : "l"(p));
    return a;
}
__device__ __forceinline__ void cp16(uint32_t saddr, const void* g) {
    asm volatile("cp.async.cg.shared.global [%0], [%1], 16;" :: "r"(saddr), "l"(g));
}
__device__ __forceinline__ void ldsm_x4(uint32_t* r, uint32_t addr) {
    asm volatile("ldmatrix.sync.aligned.m8n8.x4.shared.b16 {%0,%1,%2,%3}, [%4];"
                 : "=r"(r[0]), "=r"(r[1]), "=r"(r[2]), "=r"(r[3]) : "r"(addr));
}
// fp16-accumulator HMMA: D,C are 2 x f16x2 regs.
__device__ __forceinline__ void mma16816_f16(uint32_t* c, const uint32_t* a,
                                             uint32_t b0, uint32_t b1) {
    asm volatile(
        "mma.sync.aligned.m16n8k16.row.col.f16.f16.f16.f16 "
        "{%0,%1}, {%2,%3,%4,%5}, {%6,%7}, {%0,%1};"
        : "+r"(c[0]), "+r"(c[1])
        : "r"(a[0]), "r"(a[1]), "r"(a[2]), "r"(a[3]), "r"(b0), "r"(b1));
}
__device__ __forceinline__ uint32_t ex2h2(uint32_t v) {
    uint32_t r;
    asm volatile("ex2.approx.f16x2 %0, %1;" : "=r"(r) : "r"(v));
    return r;
}
__device__ __forceinline__ uint32_t hadd2(uint32_t a, uint32_t b) {
    uint32_t r;
    asm("add.rn.f16x2 %0, %1, %2;" : "=r"(r) : "r"(a), "r"(b));
    return r;
}
__device__ __forceinline__ float unpack_sum(uint32_t v) {
    float lo, hi;
    asm("{ .reg .b16 l, h; mov.b32 {l, h}, %2;\n\t"
        "  cvt.f32.f16 %0, l; cvt.f32.f16 %1, h; }"
        : "=f"(lo), "=f"(hi) : "r"(v));
    return lo + hi;
}

// ---------------------------------------------------------------------------
// Kernel 1: normalize, build fp16 A (scaled) and B (w = u_n + i_n).
// ---------------------------------------------------------------------------
__global__ void prep_kernel(const float* __restrict__ U, const float* __restrict__ I) {
    int row  = blockIdx.x * 8 + (threadIdx.x >> 5);
    int lane = threadIdx.x & 31;

    const float* up = U + (size_t)row * DD;
    const float* ip = I + (size_t)row * DD;
    float u0 = up[lane], u1 = up[lane + 32];
    float i0 = ip[lane], i1 = ip[lane + 32];

    float su = u0 * u0 + u1 * u1;
    float si = i0 * i0 + i1 * i1;
#pragma unroll
    for (int o = 16; o; o >>= 1) {
        su += __shfl_xor_sync(0xffffffffu, su, o);
        si += __shfl_xor_sync(0xffffffffu, si, o);
    }
    float inu = rsqrtf(fmaxf(su, 1e-24f));
    float ini = rsqrtf(fmaxf(si, 1e-24f));

    float un0 = u0 * inu, un1 = u1 * inu;
    float vn0 = i0 * ini, vn1 = i1 * ini;

    float d = un0 * vn0 + un1 * vn1;
#pragma unroll
    for (int o = 16; o; o >>= 1) d += __shfl_xor_sync(0xffffffffu, d, o);

    const float SC = LOG2E_F / TAU_F;   // GEMM output directly = log2 of each exp term
    size_t base = (size_t)row * KK;
    g_a[base + lane]      = __float2half_rn(un0 * SC);
    g_a[base + 32 + lane] = __float2half_rn(un1 * SC);
    g_b[base + lane]      = __float2half_rn(un0 + vn0);
    g_b[base + 32 + lane] = __float2half_rn(un1 + vn1);

    if (lane == 0) g_pos[row] = d * (1.0f / TAU_F);
}

// ---------------------------------------------------------------------------
// Kernel 2: fp16 mma.sync GEMM with FP16 ACCUMULATORS (testing full-rate
// HMMA.F16), 128x128 tile, K=64 resident in smem. Epilogue: ex2.approx.f16x2
// directly on packed accumulators + f16x2 partial sums -> fp32 row sums.
// 8 warps 2(M) x 4(N); warp tile 64x32.
// acc[mf][nf] = {c0: row g cols (2t4, 2t4+1), c1: row g+8 same cols}.
// ---------------------------------------------------------------------------
__global__ void __launch_bounds__(256, 2) gemm_exp_kernel() {
    extern __shared__ __align__(16) char smem[];
    const uint32_t sb = smem_u32(smem);
    const uint32_t sA = sb;                    // 16 KB
    const uint32_t sB = sb + 128 * SROW;       // 16 KB

    const int tid  = threadIdx.x;
    const int wid  = tid >> 5;
    const int lane = tid & 31;
    const int wm   = wid >> 2;                 // 0..1
    const int wn   = wid & 3;                  // 0..3
    const int bm = blockIdx.y, bn = blockIdx.x;

    const char* Ag = (const char*)g_a + (size_t)bm * 128 * (KK * 2);
    const char* Bg = (const char*)g_b + (size_t)bn * 128 * (KK * 2);

    // Load both tiles: 128 rows x 8 chunks(16B) each operand.
#pragma unroll
    for (int it = 0; it < 4; it++) {
        int idx = it * 256 + tid;              // 0..1023
        int row = idx >> 3;
        int c   = idx & 7;
        uint32_t sw = (uint32_t)(row * SROW + ((c ^ (row & 7)) << 4));
        size_t   go = (size_t)row * (KK * 2) + c * 16;
        cp16(sA + sw, Ag + go);
        cp16(sB + sw, Bg + go);
    }
    asm volatile("cp.async.commit_group;" ::: "memory");

    uint32_t acc[4][4][2];                     // f16x2 accumulators
#pragma unroll
    for (int i = 0; i < 4; i++)
#pragma unroll
        for (int j = 0; j < 4; j++) { acc[i][j][0] = 0u; acc[i][j][1] = 0u; }

    asm volatile("cp.async.wait_group 0;" ::: "memory");
    __syncthreads();

    const int lr16 = lane & 15;                // ldmatrix row within 16
    const int lhi  = lane >> 4;                // k-chunk half select

#pragma unroll
    for (int ks = 0; ks < KK / 16; ks++) {     // 4 k-steps
        const int ch = 2 * ks + lhi;           // 16B chunk index (0..7)
        uint32_t a[4][4];
#pragma unroll
        for (int mf = 0; mf < 4; mf++) {
            int row = wm * 64 + mf * 16 + lr16;
            ldsm_x4(a[mf], sA + row * SROW + ((ch ^ (row & 7)) << 4));
        }
        uint32_t bfr[2][4];
#pragma unroll
        for (int p = 0; p < 2; p++) {
            int row = wn * 32 + p * 16 + lr16;
            ldsm_x4(bfr[p], sB + row * SROW + ((ch ^ (row & 7)) << 4));
        }
        // bfr[p] = {b0(nf=2p), b0(nf=2p+1), b1(nf=2p), b1(nf=2p+1)}
#pragma unroll
        for (int mf = 0; mf < 4; mf++) {
            mma16816_f16(acc[mf][0], a[mf], bfr[0][0], bfr[0][2]);
            mma16816_f16(acc[mf][1], a[mf], bfr[0][1], bfr[0][3]);
            mma16816_f16(acc[mf][2], a[mf], bfr[1][0], bfr[1][2]);
            mma16816_f16(acc[mf][3], a[mf], bfr[1][1], bfr[1][3]);
        }
    }

    // ------- Epilogue: ex2.f16x2 directly on packed accs + row sums -------
    const int g  = lane >> 2;
    const int t4 = lane & 3;
    float rs0[4], rs1[4];
#pragma unroll
    for (int mf = 0; mf < 4; mf++) {
        uint32_t s0 = hadd2(hadd2(ex2h2(acc[mf][0][0]), ex2h2(acc[mf][1][0])),
                            hadd2(ex2h2(acc[mf][2][0]), ex2h2(acc[mf][3][0])));
        uint32_t s1 = hadd2(hadd2(ex2h2(acc[mf][0][1]), ex2h2(acc[mf][1][1])),
                            hadd2(ex2h2(acc[mf][2][1]), ex2h2(acc[mf][3][1])));
        rs0[mf] = unpack_sum(s0);              // row g
        rs1[mf] = unpack_sum(s1);              // row g+8
    }
#pragma unroll
    for (int mf = 0; mf < 4; mf++) {
        rs0[mf] += __shfl_xor_sync(0xffffffffu, rs0[mf], 1);
        rs0[mf] += __shfl_xor_sync(0xffffffffu, rs0[mf], 2);
        rs1[mf] += __shfl_xor_sync(0xffffffffu, rs1[mf], 1);
        rs1[mf] += __shfl_xor_sync(0xffffffffu, rs1[mf], 2);
    }

    __syncthreads();                           // tiles no longer needed; reuse smem
    float* red = (float*)smem;                 // [128 rows][4 wn]
    if (t4 == 0) {
#pragma unroll
        for (int mf = 0; mf < 4; mf++) {
            int r0 = wm * 64 + mf * 16 + g;
            red[r0 * 4 + wn]       = rs0[mf];
            red[(r0 + 8) * 4 + wn] = rs1[mf];
        }
    }
    __syncthreads();
    if (tid < 128) {
        float s = (red[tid * 4 + 0] + red[tid * 4 + 1]) +
                  (red[tid * 4 + 2] + red[tid * 4 + 3]);
        g_partial[(size_t)bn * NN + bm * 128 + tid] = s;   // fixed order, no atomics
    }
}

// ---------------------------------------------------------------------------
// Kernel 3: per-row total over 128 column-block partials, loss, block sums.
// ---------------------------------------------------------------------------
__global__ void reduce_kernel() {
    int r = blockIdx.x * blockDim.x + threadIdx.x;
    float t = 0.f;
#pragma unroll 8
    for (int cb = 0; cb < NN / 128; cb++) t += g_partial[(size_t)cb * NN + r];
    float lr = logf(t + EPS_F) - g_pos[r];

    __shared__ float sm[256];
    sm[threadIdx.x] = lr;
    __syncthreads();
    for (int o = 128; o; o >>= 1) {
        if (threadIdx.x < o) sm[threadIdx.x] += sm[threadIdx.x + o];
        __syncthreads();
    }
    if (threadIdx.x == 0) g_blocksum[blockIdx.x] = sm[0];
}

__global__ void final_kernel(float* __restrict__ out) {
    __shared__ float sm[64];
    int t = threadIdx.x;
    sm[t] = g_blocksum[t];
    __syncthreads();
    for (int o = 32; o; o >>= 1) {
        if (t < o) sm[t] += sm[t + o];
        __syncthreads();
    }
    if (t == 0) out[0] = sm[0] * (1.0f / (float)NN);
}

// ---------------------------------------------------------------------------
extern "C" void kernel_launch(void* const* d_in, const int* in_sizes, int n_in,
                              void* d_out, int out_size) {
    const float* U = (const float*)d_in[0];
    const float* I = (const float*)d_in[1];
    float* out = (float*)d_out;

    const int SMEM_BYTES = 2 * 128 * SROW;     // 32768
    cudaFuncSetAttribute(gemm_exp_kernel,
                         cudaFuncAttributeMaxDynamicSharedMemorySize, SMEM_BYTES);

    prep_kernel<<<NN / 8, 256>>>(U, I);

    dim3 grid(NN / 128, NN / 128);
    gemm_exp_kernel<<<grid, 256, SMEM_BYTES>>>();

    reduce_kernel<<<NN / 256, 256>>>();
    final_kernel<<<1, 64>>>(out);
}